// round 12
// baseline (speedup 1.0000x reference)
#include <cuda_runtime.h>
#include <cuda_bf16.h>

// ---------------------------------------------------------------------------
// Net_7335804141892: 3x GCSConv (out = relu(A@(xW1) + xW2 + b)) -> global avg
// pool per graph -> dense(32->2) -> softmax.
// Round 12: R11 champion (213.5us) + ONE change: gemm_dual R=2 rows/thread
// with launch_bounds(256,4). ncu showed regs=80/occ=34%/issue=42% — the GEMM
// is stall-bound with registers capping occupancy at 24 warps/SM. R=2 halves
// accumulators (16 regs) -> ~56-62 regs -> 32 warps/SM, no spill risk.
// ---------------------------------------------------------------------------

#define NN 50000
#define EE 800000
#define GG 256
#define SCAN_B 1024
#define SCAN_NB ((NN + SCAN_B - 1) / SCAN_B)   // 49

// Scratch (device globals; no allocation allowed).
__device__ __nv_bfloat16 g_h[NN * 128];  // h = x @ W1 (bf16, gathered edge-wise)
__device__ float g_a1[NN * 128];   // layer1 xW2+b -> in-place layer1 output
__device__ float g_a2[NN * 64];    // layer2 xW2+b -> in-place layer2 output
__device__ float g_a3[NN * 32];    // layer3 xW2+b (consumed by fused pool)
__device__ float g_pool[GG * 32];  // per-graph feature sums
__device__ float g_cnt [GG];       // per-graph node counts

// CSR scratch
__device__ int   g_deg [NN];        // histogram of edge_row
__device__ int   g_rp  [NN + 1];    // row pointers
__device__ int   g_cur [NN];        // fill cursors
__device__ int   g_bsum[SCAN_NB];   // block sums for scan
__device__ int   g_ssrc[EE];        // edge sources, grouped by dest row
__device__ float g_sw  [EE];        // edge weights, grouped by dest row

// ---- f32x2 packed helpers -------------------------------------------------
__device__ __forceinline__ unsigned long long pk2(float a, float b) {
    unsigned long long r;
    asm("mov.b64 %0, {%1, %2};" : "=l"(r) : "f"(a), "f"(b));
    return r;
}
__device__ __forceinline__ void fma2(unsigned long long& d,
                                     unsigned long long a,
                                     unsigned long long b) {
    asm("fma.rn.f32x2 %0, %1, %2, %0;" : "+l"(d) : "l"(a), "l"(b));
}
__device__ __forceinline__ void upk2(float& lo, float& hi, unsigned long long v) {
    asm("mov.b64 {%0, %1}, %2;" : "=f"(lo), "=f"(hi) : "l"(v));
}

// ---------------------------------------------------------------------------
// Dual GEMM: H[i,:] = bf16(X[i,:] @ W1) ;  A[i,:] = X[i,:] @ W2 + b
// R=2 rows/thread, KV=2, launch_bounds(256,4): 16 accum + 16 weight regs,
// 32 warps/SM resident.
// ---------------------------------------------------------------------------
template <int FIN, int FOUT>
__global__ void __launch_bounds__(256, 4) gemm_dual(
    const float* __restrict__ X,
    const float* __restrict__ W1,
    const float* __restrict__ W2,
    const float* __restrict__ Bv,
    __nv_bfloat16* __restrict__ H,
    float* __restrict__ A,
    int n)
{
    constexpr int TPR = FOUT / 4;       // threads covering one row (4 cols each)
    constexpr int RG  = 256 / TPR;      // row-groups per block
    constexpr int R   = 2;              // rows per thread
    constexpr int KV  = 2;              // X-vector width (k-unroll)

    extern __shared__ float sm[];
    float* sW1 = sm;
    float* sW2 = sm + FIN * FOUT;
    float* sB  = sm + 2 * FIN * FOUT;

    for (int i = threadIdx.x; i < FIN * FOUT; i += 256) {
        sW1[i] = W1[i];
        sW2[i] = W2[i];
    }
    for (int i = threadIdx.x; i < FOUT; i += 256) sB[i] = Bv[i];
    __syncthreads();

    const int c4   = (threadIdx.x % TPR) * 4;
    const int rg   = threadIdx.x / TPR;
    const int row0 = (blockIdx.x * RG + rg) * R;
    if (row0 >= n) return;

    unsigned long long acc1[R][2];
    unsigned long long acc2[R][2];
#pragma unroll
    for (int r = 0; r < R; r++) {
        acc1[r][0] = 0ull; acc1[r][1] = 0ull;
        acc2[r][0] = 0ull; acc2[r][1] = 0ull;
    }

    const bool full = (row0 + R <= n);

    if (full) {
        for (int k0 = 0; k0 < FIN; k0 += KV) {
            unsigned long long w1a[KV], w1b[KV], w2a[KV], w2b[KV];
#pragma unroll
            for (int j = 0; j < KV; j++) {
                const ulonglong2 p1 = *(const ulonglong2*)&sW1[(k0 + j) * FOUT + c4];
                const ulonglong2 p2 = *(const ulonglong2*)&sW2[(k0 + j) * FOUT + c4];
                w1a[j] = p1.x; w1b[j] = p1.y;
                w2a[j] = p2.x; w2b[j] = p2.y;
            }
#pragma unroll
            for (int r = 0; r < R; r++) {
                const float2 q = *(const float2*)&X[(size_t)(row0 + r) * FIN + k0];
                float xv[KV];
                xv[0] = q.x; xv[1] = q.y;
#pragma unroll
                for (int j = 0; j < KV; j++) {
                    const unsigned long long xx = pk2(xv[j], xv[j]);
                    fma2(acc1[r][0], xx, w1a[j]);
                    fma2(acc1[r][1], xx, w1b[j]);
                    fma2(acc2[r][0], xx, w2a[j]);
                    fma2(acc2[r][1], xx, w2b[j]);
                }
            }
        }
    } else {
        for (int k0 = 0; k0 < FIN; k0 += KV) {
            unsigned long long w1a[KV], w1b[KV], w2a[KV], w2b[KV];
#pragma unroll
            for (int j = 0; j < KV; j++) {
                const ulonglong2 p1 = *(const ulonglong2*)&sW1[(k0 + j) * FOUT + c4];
                const ulonglong2 p2 = *(const ulonglong2*)&sW2[(k0 + j) * FOUT + c4];
                w1a[j] = p1.x; w1b[j] = p1.y;
                w2a[j] = p2.x; w2b[j] = p2.y;
            }
#pragma unroll
            for (int r = 0; r < R; r++) {
                if (row0 + r >= n) break;
                const float2 q = *(const float2*)&X[(size_t)(row0 + r) * FIN + k0];
                float xv[KV];
                xv[0] = q.x; xv[1] = q.y;
#pragma unroll
                for (int j = 0; j < KV; j++) {
                    const unsigned long long xx = pk2(xv[j], xv[j]);
                    fma2(acc1[r][0], xx, w1a[j]);
                    fma2(acc1[r][1], xx, w1b[j]);
                    fma2(acc2[r][0], xx, w2a[j]);
                    fma2(acc2[r][1], xx, w2b[j]);
                }
            }
        }
    }

    const float4 bb = *(const float4*)&sB[c4];
#pragma unroll
    for (int r = 0; r < R; r++) {
        int row = row0 + r;
        if (row < n) {
            float4 o1, o2;
            upk2(o1.x, o1.y, acc1[r][0]);
            upk2(o1.z, o1.w, acc1[r][1]);
            upk2(o2.x, o2.y, acc2[r][0]);
            upk2(o2.z, o2.w, acc2[r][1]);
            o2.x += bb.x; o2.y += bb.y; o2.z += bb.z; o2.w += bb.w;
            // pack 4 fp32 -> 4 bf16 (8B store)
            __nv_bfloat162 h01 = __floats2bfloat162_rn(o1.x, o1.y);
            __nv_bfloat162 h23 = __floats2bfloat162_rn(o1.z, o1.w);
            uint2 hp;
            hp.x = *(const unsigned*)&h01;
            hp.y = *(const unsigned*)&h23;
            *(uint2*)&H[(size_t)row * FOUT + c4] = hp;
            *(float4*)&A[(size_t)row * FOUT + c4] = o2;
        }
    }
}

// ---------------------------------------------------------------------------
// CSR build kernels (run every replay; graph-capturable)
// ---------------------------------------------------------------------------
__global__ void zero_misc_kernel(int n)
{
    int i = blockIdx.x * blockDim.x + threadIdx.x;
    if (i < n)       g_deg[i] = 0;
    if (i < GG * 32) g_pool[i] = 0.f;
    if (i < GG)      g_cnt[i]  = 0.f;
}

__global__ void hist_kernel(const int* __restrict__ er, int E)
{
    int e = blockIdx.x * blockDim.x + threadIdx.x;
    if (e < E) atomicAdd(&g_deg[__ldg(&er[e])], 1);
}

// block-level exclusive scan of g_deg -> g_rp (block-local), block totals -> g_bsum
__global__ void __launch_bounds__(SCAN_B) scan1_kernel(int n)
{
    __shared__ int wsum[32];
    int i = blockIdx.x * SCAN_B + threadIdx.x;
    int v = (i < n) ? g_deg[i] : 0;
    int lane = threadIdx.x & 31, wid = threadIdx.x >> 5;

    int s = v;
#pragma unroll
    for (int o = 1; o < 32; o <<= 1) {
        int t = __shfl_up_sync(0xFFFFFFFFu, s, o);
        if (lane >= o) s += t;
    }
    if (lane == 31) wsum[wid] = s;
    __syncthreads();
    if (wid == 0) {
        int ws = wsum[lane];
#pragma unroll
        for (int o = 1; o < 32; o <<= 1) {
            int t = __shfl_up_sync(0xFFFFFFFFu, ws, o);
            if (lane >= o) ws += t;
        }
        wsum[lane] = ws;
    }
    __syncthreads();
    int excl = s - v + ((wid > 0) ? wsum[wid - 1] : 0);
    if (i < n) g_rp[i] = excl;
    if (threadIdx.x == 0) g_bsum[blockIdx.x] = wsum[31];
}

// one-warp scan of the SCAN_NB block sums
__global__ void scan2_kernel(int nb, int n, int E)
{
    int lane = threadIdx.x;
    int carry = 0;
    for (int base = 0; base < nb; base += 32) {
        int i = base + lane;
        int v = (i < nb) ? g_bsum[i] : 0;
        int s = v;
#pragma unroll
        for (int o = 1; o < 32; o <<= 1) {
            int t = __shfl_up_sync(0xFFFFFFFFu, s, o);
            if (lane >= o) s += t;
        }
        if (i < nb) g_bsum[i] = s - v + carry;
        carry += __shfl_sync(0xFFFFFFFFu, s, 31);
    }
    if (lane == 0) g_rp[n] = E;
}

__global__ void __launch_bounds__(SCAN_B) scan3_kernel(int n)
{
    int i = blockIdx.x * SCAN_B + threadIdx.x;
    if (i < n) {
        int v = g_rp[i] + g_bsum[blockIdx.x];
        g_rp[i]  = v;
        g_cur[i] = v;
    }
}

__global__ void fill_kernel(const int* __restrict__ er,
                            const int* __restrict__ ec,
                            const float* __restrict__ ew, int E)
{
    int e = blockIdx.x * blockDim.x + threadIdx.x;
    if (e >= E) return;
    int r   = __ldg(&er[e]);
    int pos = atomicAdd(&g_cur[r], 1);
    g_ssrc[pos] = __ldg(&ec[e]);
    g_sw[pos]   = __ldg(&ew[e]);
}

// ---------------------------------------------------------------------------
// Gather aggregation: one warp per destination row.
//   out[r,:] = relu( sum_{e in row r} w_e * bf16->f32(H[src_e,:]) + A[r,:] )
// ---------------------------------------------------------------------------
template <int FOUT, bool POOL>
__global__ void __launch_bounds__(256) agg_rows(
    const __nv_bfloat16* __restrict__ H,
    float* __restrict__ A,                 // in: xW2+b, out: activated result
    const int* __restrict__ seg,
    int n)
{
    constexpr int TPR = FOUT / 4;          // 32 / 16 / 8
    constexpr int EPI = 32 / TPR;          // 1 / 2 / 4

    int warp = (blockIdx.x * blockDim.x + threadIdx.x) >> 5;
    if (warp >= n) return;
    int lane = threadIdx.x & 31;
    int cl   = lane % TPR;                 // column chunk (4 bf16)
    int es   = lane / TPR;                 // edge slot

    int begin = __ldg(&g_rp[warp]);
    int end   = __ldg(&g_rp[warp + 1]);

    float4 acc = make_float4(0.f, 0.f, 0.f, 0.f);
#pragma unroll 2
    for (int i = begin + es; i < end; i += EPI) {
        int   src = __ldg(&g_ssrc[i]);
        float w   = __ldg(&g_sw[i]);
        const uint2 hp = *(const uint2*)&H[(size_t)src * FOUT + cl * 4];
        float2 f01 = __bfloat1622float2(*(const __nv_bfloat162*)&hp.x);
        float2 f23 = __bfloat1622float2(*(const __nv_bfloat162*)&hp.y);
        acc.x = fmaf(w, f01.x, acc.x);
        acc.y = fmaf(w, f01.y, acc.y);
        acc.z = fmaf(w, f23.x, acc.z);
        acc.w = fmaf(w, f23.y, acc.w);
    }

    // reduce edge-slot partials (lanes with equal cl)
#pragma unroll
    for (int off = TPR; off < 32; off <<= 1) {
        acc.x += __shfl_xor_sync(0xFFFFFFFFu, acc.x, off);
        acc.y += __shfl_xor_sync(0xFFFFFFFFu, acc.y, off);
        acc.z += __shfl_xor_sync(0xFFFFFFFFu, acc.z, off);
        acc.w += __shfl_xor_sync(0xFFFFFFFFu, acc.w, off);
    }

    if (es == 0) {
        const float4 base = *(const float4*)&A[(size_t)warp * FOUT + cl * 4];
        float4 o;
        o.x = fmaxf(acc.x + base.x, 0.f);
        o.y = fmaxf(acc.y + base.y, 0.f);
        o.z = fmaxf(acc.z + base.z, 0.f);
        o.w = fmaxf(acc.w + base.w, 0.f);
        if (POOL) {
            int g = __ldg(&seg[warp]);
            float* dst = &g_pool[g * 32 + cl * 4];
            asm volatile("red.global.add.v4.f32 [%0], {%1,%2,%3,%4};"
                         :: "l"(dst), "f"(o.x), "f"(o.y), "f"(o.z), "f"(o.w)
                         : "memory");
            if (cl == 0) atomicAdd(&g_cnt[g], 1.0f);
        } else {
            *(float4*)&A[(size_t)warp * FOUT + cl * 4] = o;
        }
    }
}

__global__ void head_kernel(const float* __restrict__ wd,
                            const float* __restrict__ bd,
                            float* __restrict__ out)
{
    int g = threadIdx.x;   // 256 threads, one per graph
    float cnt = fmaxf(g_cnt[g], 1.0f);
    float inv = 1.0f / cnt;
    float z0 = __ldg(&bd[0]);
    float z1 = __ldg(&bd[1]);
#pragma unroll
    for (int k = 0; k < 32; k++) {
        float p = g_pool[g * 32 + k] * inv;
        z0 = fmaf(p, __ldg(&wd[k * 2 + 0]), z0);
        z1 = fmaf(p, __ldg(&wd[k * 2 + 1]), z1);
    }
    float m  = fmaxf(z0, z1);
    float e0 = __expf(z0 - m);
    float e1 = __expf(z1 - m);
    float s  = 1.0f / (e0 + e1);
    out[g * 2 + 0] = e0 * s;
    out[g * 2 + 1] = e1 * s;
}

// ---------------------------------------------------------------------------
// Launch. gemm_dual<30,128> stays at profile index 3 (before/after evidence).
// ---------------------------------------------------------------------------
extern "C" void kernel_launch(void* const* d_in, const int* in_sizes, int n_in,
                              void* d_out, int out_size)
{
    const float* x    = (const float*)d_in[0];
    const float* ew   = (const float*)d_in[1];
    const int*   er   = (const int*)  d_in[2];
    const int*   ec   = (const int*)  d_in[3];
    const int*   seg  = (const int*)  d_in[4];
    const float* w1_1 = (const float*)d_in[5];
    const float* w2_1 = (const float*)d_in[6];
    const float* b_1  = (const float*)d_in[7];
    const float* w1_2 = (const float*)d_in[8];
    const float* w2_2 = (const float*)d_in[9];
    const float* b_2  = (const float*)d_in[10];
    const float* w1_3 = (const float*)d_in[11];
    const float* w2_3 = (const float*)d_in[12];
    const float* b_3  = (const float*)d_in[13];
    const float* wd   = (const float*)d_in[14];
    const float* bd   = (const float*)d_in[15];
    float* out = (float*)d_out;

    const int n = in_sizes[0] / 30;   // 50000
    const int E = in_sizes[1];        // 800000

    __nv_bfloat16* H;
    float *A1, *A2, *A3;
    cudaGetSymbolAddress((void**)&H,  g_h);
    cudaGetSymbolAddress((void**)&A1, g_a1);
    cudaGetSymbolAddress((void**)&A2, g_a2);
    cudaGetSymbolAddress((void**)&A3, g_a3);

    // dynamic smem sizes: (2*FIN*FOUT + FOUT) * 4 bytes
    const int sm1 = (2 * 30  * 128 + 128) * 4;   // 31232
    const int sm2 = (2 * 128 * 64  + 64)  * 4;   // 65792 (>48KB: opt in)
    const int sm3 = (2 * 64  * 32  + 32)  * 4;   // 16512

    cudaFuncSetAttribute(gemm_dual<128, 64>,
                         cudaFuncAttributeMaxDynamicSharedMemorySize, sm2);

    const int agg_blocks = (n * 32 + 255) / 256;

    // ---- CSR build start ----
    zero_misc_kernel<<<(n + 255) / 256, 256>>>(n);                 // 0
    hist_kernel<<<(E + 255) / 256, 256>>>(er, E);                  // 1
    scan1_kernel<<<SCAN_NB, SCAN_B>>>(n);                          // 2

    // ---- Layer-1 GEMM (independent of CSR) at profile index 3 ----
    {
        int rows_per_block = (256 / (128 / 4)) * 2;  // 16
        int blocks = (n + rows_per_block - 1) / rows_per_block;
        gemm_dual<30, 128><<<blocks, 256, sm1>>>(x, w1_1, w2_1, b_1, H, A1, n); // 3
    }

    // ---- CSR build finish ----
    scan2_kernel<<<1, 32>>>(SCAN_NB, n, E);                        // 4
    scan3_kernel<<<SCAN_NB, SCAN_B>>>(n);                          // 5
    fill_kernel<<<(E + 255) / 256, 256>>>(er, ec, ew, E);          // 6

    // ---- Layer 1 aggregation ----
    agg_rows<128, false><<<agg_blocks, 256>>>(H, A1, seg, n);

    // ---- Layer 2: 128 -> 64 ----
    {
        int rows_per_block = (256 / (64 / 4)) * 2;   // 32
        int blocks = (n + rows_per_block - 1) / rows_per_block;
        gemm_dual<128, 64><<<blocks, 256, sm2>>>(A1, w1_2, w2_2, b_2, H, A2, n);
        agg_rows<64, false><<<agg_blocks, 256>>>(H, A2, seg, n);
    }
    // ---- Layer 3: 64 -> 32 (aggregation fuses relu + global pool) ----
    {
        int rows_per_block = (256 / (32 / 4)) * 2;   // 64
        int blocks = (n + rows_per_block - 1) / rows_per_block;
        gemm_dual<64, 32><<<blocks, 256, sm3>>>(A2, w1_3, w2_3, b_3, H, A3, n);
        agg_rows<32, true><<<agg_blocks, 256>>>(H, A3, seg, n);
    }

    // ---- Head ----
    head_kernel<<<1, GG>>>(wd, bd, out);
}

// round 13
// speedup vs baseline: 1.1570x; 1.1570x over previous
#include <cuda_runtime.h>
#include <cuda_bf16.h>

// ---------------------------------------------------------------------------
// Net_7335804141892: 3x GCSConv (out = relu(A@(xW1) + xW2 + b)) -> global avg
// pool per graph -> dense(32->2) -> softmax.
// Round 13: exact R11 champion (213.5us: R=4/KV=2/launch_bounds(256,3) dual
// GEMM, bf16 H, separate ssrc/sw) + scan2 fused into scan3 (R8-measured at
// ~6us standalone), deleting the 4.4us single-warp straggler + one launch.
// R12's R=2 experiment proved the GEMM is LDS-throughput-bound, not
// occupancy-bound — R=4 restored.
// ---------------------------------------------------------------------------

#define NN 50000
#define EE 800000
#define GG 256
#define SCAN_B 1024
#define SCAN_NB ((NN + SCAN_B - 1) / SCAN_B)   // 49

// Scratch (device globals; no allocation allowed).
__device__ __nv_bfloat16 g_h[NN * 128];  // h = x @ W1 (bf16, gathered edge-wise)
__device__ float g_a1[NN * 128];   // layer1 xW2+b -> in-place layer1 output
__device__ float g_a2[NN * 64];    // layer2 xW2+b -> in-place layer2 output
__device__ float g_a3[NN * 32];    // layer3 xW2+b (consumed by fused pool)
__device__ float g_pool[GG * 32];  // per-graph feature sums
__device__ float g_cnt [GG];       // per-graph node counts

// CSR scratch
__device__ int   g_deg [NN];        // histogram of edge_row
__device__ int   g_rp  [NN + 1];    // row pointers
__device__ int   g_cur [NN];        // fill cursors
__device__ int   g_bsum[SCAN_NB];   // block sums for scan
__device__ int   g_ssrc[EE];        // edge sources, grouped by dest row
__device__ float g_sw  [EE];        // edge weights, grouped by dest row

// ---- f32x2 packed helpers -------------------------------------------------
__device__ __forceinline__ unsigned long long pk2(float a, float b) {
    unsigned long long r;
    asm("mov.b64 %0, {%1, %2};" : "=l"(r) : "f"(a), "f"(b));
    return r;
}
__device__ __forceinline__ void fma2(unsigned long long& d,
                                     unsigned long long a,
                                     unsigned long long b) {
    asm("fma.rn.f32x2 %0, %1, %2, %0;" : "+l"(d) : "l"(a), "l"(b));
}
__device__ __forceinline__ void upk2(float& lo, float& hi, unsigned long long v) {
    asm("mov.b64 {%0, %1}, %2;" : "=f"(lo), "=f"(hi) : "l"(v));
}

// ---------------------------------------------------------------------------
// Dual GEMM: H[i,:] = bf16(X[i,:] @ W1) ;  A[i,:] = X[i,:] @ W2 + b
// R=4 rows/thread, KV=2, launch_bounds(256,3) — the champion config.
// ---------------------------------------------------------------------------
template <int FIN, int FOUT>
__global__ void __launch_bounds__(256, 3) gemm_dual(
    const float* __restrict__ X,
    const float* __restrict__ W1,
    const float* __restrict__ W2,
    const float* __restrict__ Bv,
    __nv_bfloat16* __restrict__ H,
    float* __restrict__ A,
    int n)
{
    constexpr int TPR = FOUT / 4;       // threads covering one row (4 cols each)
    constexpr int RG  = 256 / TPR;      // row-groups per block
    constexpr int R   = 4;              // rows per thread
    constexpr int KV  = 2;              // X-vector width (k-unroll)

    extern __shared__ float sm[];
    float* sW1 = sm;
    float* sW2 = sm + FIN * FOUT;
    float* sB  = sm + 2 * FIN * FOUT;

    for (int i = threadIdx.x; i < FIN * FOUT; i += 256) {
        sW1[i] = W1[i];
        sW2[i] = W2[i];
    }
    for (int i = threadIdx.x; i < FOUT; i += 256) sB[i] = Bv[i];
    __syncthreads();

    const int c4   = (threadIdx.x % TPR) * 4;
    const int rg   = threadIdx.x / TPR;
    const int row0 = (blockIdx.x * RG + rg) * R;
    if (row0 >= n) return;

    unsigned long long acc1[R][2];
    unsigned long long acc2[R][2];
#pragma unroll
    for (int r = 0; r < R; r++) {
        acc1[r][0] = 0ull; acc1[r][1] = 0ull;
        acc2[r][0] = 0ull; acc2[r][1] = 0ull;
    }

    const bool full = (row0 + R <= n);

    if (full) {
        for (int k0 = 0; k0 < FIN; k0 += KV) {
            unsigned long long w1a[KV], w1b[KV], w2a[KV], w2b[KV];
#pragma unroll
            for (int j = 0; j < KV; j++) {
                const ulonglong2 p1 = *(const ulonglong2*)&sW1[(k0 + j) * FOUT + c4];
                const ulonglong2 p2 = *(const ulonglong2*)&sW2[(k0 + j) * FOUT + c4];
                w1a[j] = p1.x; w1b[j] = p1.y;
                w2a[j] = p2.x; w2b[j] = p2.y;
            }
#pragma unroll
            for (int r = 0; r < R; r++) {
                const float2 q = *(const float2*)&X[(size_t)(row0 + r) * FIN + k0];
                float xv[KV];
                xv[0] = q.x; xv[1] = q.y;
#pragma unroll
                for (int j = 0; j < KV; j++) {
                    const unsigned long long xx = pk2(xv[j], xv[j]);
                    fma2(acc1[r][0], xx, w1a[j]);
                    fma2(acc1[r][1], xx, w1b[j]);
                    fma2(acc2[r][0], xx, w2a[j]);
                    fma2(acc2[r][1], xx, w2b[j]);
                }
            }
        }
    } else {
        for (int k0 = 0; k0 < FIN; k0 += KV) {
            unsigned long long w1a[KV], w1b[KV], w2a[KV], w2b[KV];
#pragma unroll
            for (int j = 0; j < KV; j++) {
                const ulonglong2 p1 = *(const ulonglong2*)&sW1[(k0 + j) * FOUT + c4];
                const ulonglong2 p2 = *(const ulonglong2*)&sW2[(k0 + j) * FOUT + c4];
                w1a[j] = p1.x; w1b[j] = p1.y;
                w2a[j] = p2.x; w2b[j] = p2.y;
            }
#pragma unroll
            for (int r = 0; r < R; r++) {
                if (row0 + r >= n) break;
                const float2 q = *(const float2*)&X[(size_t)(row0 + r) * FIN + k0];
                float xv[KV];
                xv[0] = q.x; xv[1] = q.y;
#pragma unroll
                for (int j = 0; j < KV; j++) {
                    const unsigned long long xx = pk2(xv[j], xv[j]);
                    fma2(acc1[r][0], xx, w1a[j]);
                    fma2(acc1[r][1], xx, w1b[j]);
                    fma2(acc2[r][0], xx, w2a[j]);
                    fma2(acc2[r][1], xx, w2b[j]);
                }
            }
        }
    }

    const float4 bb = *(const float4*)&sB[c4];
#pragma unroll
    for (int r = 0; r < R; r++) {
        int row = row0 + r;
        if (row < n) {
            float4 o1, o2;
            upk2(o1.x, o1.y, acc1[r][0]);
            upk2(o1.z, o1.w, acc1[r][1]);
            upk2(o2.x, o2.y, acc2[r][0]);
            upk2(o2.z, o2.w, acc2[r][1]);
            o2.x += bb.x; o2.y += bb.y; o2.z += bb.z; o2.w += bb.w;
            // pack 4 fp32 -> 4 bf16 (8B store)
            __nv_bfloat162 h01 = __floats2bfloat162_rn(o1.x, o1.y);
            __nv_bfloat162 h23 = __floats2bfloat162_rn(o1.z, o1.w);
            uint2 hp;
            hp.x = *(const unsigned*)&h01;
            hp.y = *(const unsigned*)&h23;
            *(uint2*)&H[(size_t)row * FOUT + c4] = hp;
            *(float4*)&A[(size_t)row * FOUT + c4] = o2;
        }
    }
}

// ---------------------------------------------------------------------------
// CSR build kernels (run every replay; graph-capturable)
// ---------------------------------------------------------------------------
__global__ void zero_misc_kernel(int n)
{
    int i = blockIdx.x * blockDim.x + threadIdx.x;
    if (i < n)       g_deg[i] = 0;
    if (i < GG * 32) g_pool[i] = 0.f;
    if (i < GG)      g_cnt[i]  = 0.f;
}

__global__ void hist_kernel(const int* __restrict__ er, int E)
{
    int e = blockIdx.x * blockDim.x + threadIdx.x;
    if (e < E) atomicAdd(&g_deg[__ldg(&er[e])], 1);
}

// block-level exclusive scan of g_deg -> g_rp (block-local), block totals -> g_bsum
__global__ void __launch_bounds__(SCAN_B) scan1_kernel(int n)
{
    __shared__ int wsum[32];
    int i = blockIdx.x * SCAN_B + threadIdx.x;
    int v = (i < n) ? g_deg[i] : 0;
    int lane = threadIdx.x & 31, wid = threadIdx.x >> 5;

    int s = v;
#pragma unroll
    for (int o = 1; o < 32; o <<= 1) {
        int t = __shfl_up_sync(0xFFFFFFFFu, s, o);
        if (lane >= o) s += t;
    }
    if (lane == 31) wsum[wid] = s;
    __syncthreads();
    if (wid == 0) {
        int ws = wsum[lane];
#pragma unroll
        for (int o = 1; o < 32; o <<= 1) {
            int t = __shfl_up_sync(0xFFFFFFFFu, ws, o);
            if (lane >= o) ws += t;
        }
        wsum[lane] = ws;
    }
    __syncthreads();
    int excl = s - v + ((wid > 0) ? wsum[wid - 1] : 0);
    if (i < n) g_rp[i] = excl;
    if (threadIdx.x == 0) g_bsum[blockIdx.x] = wsum[31];
}

// scan3 with inline block-prefix: each block reduces g_bsum[0..blockIdx-1]
// (fuses the old single-warp scan2 kernel away; R8-measured ~6us standalone)
__global__ void __launch_bounds__(SCAN_B) scan3_kernel(int n, int E)
{
    __shared__ int pfx;
    if (threadIdx.x < 32) {
        int s = 0;
        for (int j = threadIdx.x; j < blockIdx.x; j += 32) s += g_bsum[j];
#pragma unroll
        for (int o = 16; o > 0; o >>= 1)
            s += __shfl_xor_sync(0xFFFFFFFFu, s, o);
        if (threadIdx.x == 0) pfx = s;
    }
    __syncthreads();
    int i = blockIdx.x * SCAN_B + threadIdx.x;
    if (i < n) {
        int v = g_rp[i] + pfx;
        g_rp[i]  = v;
        g_cur[i] = v;
    }
    if (blockIdx.x == 0 && threadIdx.x == 0) g_rp[n] = E;
}

__global__ void fill_kernel(const int* __restrict__ er,
                            const int* __restrict__ ec,
                            const float* __restrict__ ew, int E)
{
    int e = blockIdx.x * blockDim.x + threadIdx.x;
    if (e >= E) return;
    int r   = __ldg(&er[e]);
    int pos = atomicAdd(&g_cur[r], 1);
    g_ssrc[pos] = __ldg(&ec[e]);
    g_sw[pos]   = __ldg(&ew[e]);
}

// ---------------------------------------------------------------------------
// Gather aggregation: one warp per destination row.
//   out[r,:] = relu( sum_{e in row r} w_e * bf16->f32(H[src_e,:]) + A[r,:] )
// ---------------------------------------------------------------------------
template <int FOUT, bool POOL>
__global__ void __launch_bounds__(256) agg_rows(
    const __nv_bfloat16* __restrict__ H,
    float* __restrict__ A,                 // in: xW2+b, out: activated result
    const int* __restrict__ seg,
    int n)
{
    constexpr int TPR = FOUT / 4;          // 32 / 16 / 8
    constexpr int EPI = 32 / TPR;          // 1 / 2 / 4

    int warp = (blockIdx.x * blockDim.x + threadIdx.x) >> 5;
    if (warp >= n) return;
    int lane = threadIdx.x & 31;
    int cl   = lane % TPR;                 // column chunk (4 bf16)
    int es   = lane / TPR;                 // edge slot

    int begin = __ldg(&g_rp[warp]);
    int end   = __ldg(&g_rp[warp + 1]);

    float4 acc = make_float4(0.f, 0.f, 0.f, 0.f);
#pragma unroll 2
    for (int i = begin + es; i < end; i += EPI) {
        int   src = __ldg(&g_ssrc[i]);
        float w   = __ldg(&g_sw[i]);
        const uint2 hp = *(const uint2*)&H[(size_t)src * FOUT + cl * 4];
        float2 f01 = __bfloat1622float2(*(const __nv_bfloat162*)&hp.x);
        float2 f23 = __bfloat1622float2(*(const __nv_bfloat162*)&hp.y);
        acc.x = fmaf(w, f01.x, acc.x);
        acc.y = fmaf(w, f01.y, acc.y);
        acc.z = fmaf(w, f23.x, acc.z);
        acc.w = fmaf(w, f23.y, acc.w);
    }

    // reduce edge-slot partials (lanes with equal cl)
#pragma unroll
    for (int off = TPR; off < 32; off <<= 1) {
        acc.x += __shfl_xor_sync(0xFFFFFFFFu, acc.x, off);
        acc.y += __shfl_xor_sync(0xFFFFFFFFu, acc.y, off);
        acc.z += __shfl_xor_sync(0xFFFFFFFFu, acc.z, off);
        acc.w += __shfl_xor_sync(0xFFFFFFFFu, acc.w, off);
    }

    if (es == 0) {
        const float4 base = *(const float4*)&A[(size_t)warp * FOUT + cl * 4];
        float4 o;
        o.x = fmaxf(acc.x + base.x, 0.f);
        o.y = fmaxf(acc.y + base.y, 0.f);
        o.z = fmaxf(acc.z + base.z, 0.f);
        o.w = fmaxf(acc.w + base.w, 0.f);
        if (POOL) {
            int g = __ldg(&seg[warp]);
            float* dst = &g_pool[g * 32 + cl * 4];
            asm volatile("red.global.add.v4.f32 [%0], {%1,%2,%3,%4};"
                         :: "l"(dst), "f"(o.x), "f"(o.y), "f"(o.z), "f"(o.w)
                         : "memory");
            if (cl == 0) atomicAdd(&g_cnt[g], 1.0f);
        } else {
            *(float4*)&A[(size_t)warp * FOUT + cl * 4] = o;
        }
    }
}

__global__ void head_kernel(const float* __restrict__ wd,
                            const float* __restrict__ bd,
                            float* __restrict__ out)
{
    int g = threadIdx.x;   // 256 threads, one per graph
    float cnt = fmaxf(g_cnt[g], 1.0f);
    float inv = 1.0f / cnt;
    float z0 = __ldg(&bd[0]);
    float z1 = __ldg(&bd[1]);
#pragma unroll
    for (int k = 0; k < 32; k++) {
        float p = g_pool[g * 32 + k] * inv;
        z0 = fmaf(p, __ldg(&wd[k * 2 + 0]), z0);
        z1 = fmaf(p, __ldg(&wd[k * 2 + 1]), z1);
    }
    float m  = fmaxf(z0, z1);
    float e0 = __expf(z0 - m);
    float e1 = __expf(z1 - m);
    float s  = 1.0f / (e0 + e1);
    out[g * 2 + 0] = e0 * s;
    out[g * 2 + 1] = e1 * s;
}

// ---------------------------------------------------------------------------
// Launch. gemm_dual<30,128> stays at profile index 3.
// ---------------------------------------------------------------------------
extern "C" void kernel_launch(void* const* d_in, const int* in_sizes, int n_in,
                              void* d_out, int out_size)
{
    const float* x    = (const float*)d_in[0];
    const float* ew   = (const float*)d_in[1];
    const int*   er   = (const int*)  d_in[2];
    const int*   ec   = (const int*)  d_in[3];
    const int*   seg  = (const int*)  d_in[4];
    const float* w1_1 = (const float*)d_in[5];
    const float* w2_1 = (const float*)d_in[6];
    const float* b_1  = (const float*)d_in[7];
    const float* w1_2 = (const float*)d_in[8];
    const float* w2_2 = (const float*)d_in[9];
    const float* b_2  = (const float*)d_in[10];
    const float* w1_3 = (const float*)d_in[11];
    const float* w2_3 = (const float*)d_in[12];
    const float* b_3  = (const float*)d_in[13];
    const float* wd   = (const float*)d_in[14];
    const float* bd   = (const float*)d_in[15];
    float* out = (float*)d_out;

    const int n = in_sizes[0] / 30;   // 50000
    const int E = in_sizes[1];        // 800000

    __nv_bfloat16* H;
    float *A1, *A2, *A3;
    cudaGetSymbolAddress((void**)&H,  g_h);
    cudaGetSymbolAddress((void**)&A1, g_a1);
    cudaGetSymbolAddress((void**)&A2, g_a2);
    cudaGetSymbolAddress((void**)&A3, g_a3);

    // dynamic smem sizes: (2*FIN*FOUT + FOUT) * 4 bytes
    const int sm1 = (2 * 30  * 128 + 128) * 4;   // 31232
    const int sm2 = (2 * 128 * 64  + 64)  * 4;   // 65792 (>48KB: opt in)
    const int sm3 = (2 * 64  * 32  + 32)  * 4;   // 16512

    cudaFuncSetAttribute(gemm_dual<128, 64>,
                         cudaFuncAttributeMaxDynamicSharedMemorySize, sm2);

    const int agg_blocks = (n * 32 + 255) / 256;

    // ---- CSR build start ----
    zero_misc_kernel<<<(n + 255) / 256, 256>>>(n);                 // 0
    hist_kernel<<<(E + 255) / 256, 256>>>(er, E);                  // 1
    scan1_kernel<<<SCAN_NB, SCAN_B>>>(n);                          // 2

    // ---- Layer-1 GEMM (independent of CSR) at profile index 3 ----
    {
        int rows_per_block = (256 / (128 / 4)) * 4;  // 32
        int blocks = (n + rows_per_block - 1) / rows_per_block;
        gemm_dual<30, 128><<<blocks, 256, sm1>>>(x, w1_1, w2_1, b_1, H, A1, n); // 3
    }

    // ---- CSR build finish ----
    scan3_kernel<<<SCAN_NB, SCAN_B>>>(n, E);                       // 4
    fill_kernel<<<(E + 255) / 256, 256>>>(er, ec, ew, E);          // 5

    // ---- Layer 1 aggregation ----
    agg_rows<128, false><<<agg_blocks, 256>>>(H, A1, seg, n);

    // ---- Layer 2: 128 -> 64 ----
    {
        int rows_per_block = (256 / (64 / 4)) * 4;   // 64
        int blocks = (n + rows_per_block - 1) / rows_per_block;
        gemm_dual<128, 64><<<blocks, 256, sm2>>>(A1, w1_2, w2_2, b_2, H, A2, n);
        agg_rows<64, false><<<agg_blocks, 256>>>(H, A2, seg, n);
    }
    // ---- Layer 3: 64 -> 32 (aggregation fuses relu + global pool) ----
    {
        int rows_per_block = (256 / (32 / 4)) * 4;   // 128
        int blocks = (n + rows_per_block - 1) / rows_per_block;
        gemm_dual<64, 32><<<blocks, 256, sm3>>>(A2, w1_3, w2_3, b_3, H, A3, n);
        agg_rows<32, true><<<agg_blocks, 256>>>(H, A3, seg, n);
    }

    // ---- Head ----
    head_kernel<<<1, GG>>>(wd, bd, out);
}

// round 14
// speedup vs baseline: 1.1806x; 1.0204x over previous
#include <cuda_runtime.h>
#include <cuda_bf16.h>

// ---------------------------------------------------------------------------
// Net_7335804141892: 3x GCSConv (out = relu(A@(xW1) + xW2 + b)) -> global avg
// pool per graph -> dense(32->2) -> softmax.
// Round 14: R13 champion (212.4us) + two-stream fork: CSR build chain runs on
// a side stream concurrently with the independent layer-1 GEMM. Re-audit of
// R4/R5 showed the fork was NEUTRAL (the fused scan was the regressor), so
// this is the first clean test of CSR/GEMM overlap on the champion.
// ---------------------------------------------------------------------------

#define NN 50000
#define EE 800000
#define GG 256
#define SCAN_B 1024
#define SCAN_NB ((NN + SCAN_B - 1) / SCAN_B)   // 49

// Scratch (device globals; no allocation allowed).
__device__ __nv_bfloat16 g_h[NN * 128];  // h = x @ W1 (bf16, gathered edge-wise)
__device__ float g_a1[NN * 128];   // layer1 xW2+b -> in-place layer1 output
__device__ float g_a2[NN * 64];    // layer2 xW2+b -> in-place layer2 output
__device__ float g_a3[NN * 32];    // layer3 xW2+b (consumed by fused pool)
__device__ float g_pool[GG * 32];  // per-graph feature sums
__device__ float g_cnt [GG];       // per-graph node counts

// CSR scratch
__device__ int   g_deg [NN];        // histogram of edge_row
__device__ int   g_rp  [NN + 1];    // row pointers
__device__ int   g_cur [NN];        // fill cursors
__device__ int   g_bsum[SCAN_NB];   // block sums for scan
__device__ int   g_ssrc[EE];        // edge sources, grouped by dest row
__device__ float g_sw  [EE];        // edge weights, grouped by dest row

// ---- f32x2 packed helpers -------------------------------------------------
__device__ __forceinline__ unsigned long long pk2(float a, float b) {
    unsigned long long r;
    asm("mov.b64 %0, {%1, %2};" : "=l"(r) : "f"(a), "f"(b));
    return r;
}
__device__ __forceinline__ void fma2(unsigned long long& d,
                                     unsigned long long a,
                                     unsigned long long b) {
    asm("fma.rn.f32x2 %0, %1, %2, %0;" : "+l"(d) : "l"(a), "l"(b));
}
__device__ __forceinline__ void upk2(float& lo, float& hi, unsigned long long v) {
    asm("mov.b64 {%0, %1}, %2;" : "=f"(lo), "=f"(hi) : "l"(v));
}

// ---------------------------------------------------------------------------
// Dual GEMM: H[i,:] = bf16(X[i,:] @ W1) ;  A[i,:] = X[i,:] @ W2 + b
// R=4 rows/thread, KV=2, launch_bounds(256,3) — the champion config.
// ---------------------------------------------------------------------------
template <int FIN, int FOUT>
__global__ void __launch_bounds__(256, 3) gemm_dual(
    const float* __restrict__ X,
    const float* __restrict__ W1,
    const float* __restrict__ W2,
    const float* __restrict__ Bv,
    __nv_bfloat16* __restrict__ H,
    float* __restrict__ A,
    int n)
{
    constexpr int TPR = FOUT / 4;       // threads covering one row (4 cols each)
    constexpr int RG  = 256 / TPR;      // row-groups per block
    constexpr int R   = 4;              // rows per thread
    constexpr int KV  = 2;              // X-vector width (k-unroll)

    extern __shared__ float sm[];
    float* sW1 = sm;
    float* sW2 = sm + FIN * FOUT;
    float* sB  = sm + 2 * FIN * FOUT;

    for (int i = threadIdx.x; i < FIN * FOUT; i += 256) {
        sW1[i] = W1[i];
        sW2[i] = W2[i];
    }
    for (int i = threadIdx.x; i < FOUT; i += 256) sB[i] = Bv[i];
    __syncthreads();

    const int c4   = (threadIdx.x % TPR) * 4;
    const int rg   = threadIdx.x / TPR;
    const int row0 = (blockIdx.x * RG + rg) * R;
    if (row0 >= n) return;

    unsigned long long acc1[R][2];
    unsigned long long acc2[R][2];
#pragma unroll
    for (int r = 0; r < R; r++) {
        acc1[r][0] = 0ull; acc1[r][1] = 0ull;
        acc2[r][0] = 0ull; acc2[r][1] = 0ull;
    }

    const bool full = (row0 + R <= n);

    if (full) {
        for (int k0 = 0; k0 < FIN; k0 += KV) {
            unsigned long long w1a[KV], w1b[KV], w2a[KV], w2b[KV];
#pragma unroll
            for (int j = 0; j < KV; j++) {
                const ulonglong2 p1 = *(const ulonglong2*)&sW1[(k0 + j) * FOUT + c4];
                const ulonglong2 p2 = *(const ulonglong2*)&sW2[(k0 + j) * FOUT + c4];
                w1a[j] = p1.x; w1b[j] = p1.y;
                w2a[j] = p2.x; w2b[j] = p2.y;
            }
#pragma unroll
            for (int r = 0; r < R; r++) {
                const float2 q = *(const float2*)&X[(size_t)(row0 + r) * FIN + k0];
                float xv[KV];
                xv[0] = q.x; xv[1] = q.y;
#pragma unroll
                for (int j = 0; j < KV; j++) {
                    const unsigned long long xx = pk2(xv[j], xv[j]);
                    fma2(acc1[r][0], xx, w1a[j]);
                    fma2(acc1[r][1], xx, w1b[j]);
                    fma2(acc2[r][0], xx, w2a[j]);
                    fma2(acc2[r][1], xx, w2b[j]);
                }
            }
        }
    } else {
        for (int k0 = 0; k0 < FIN; k0 += KV) {
            unsigned long long w1a[KV], w1b[KV], w2a[KV], w2b[KV];
#pragma unroll
            for (int j = 0; j < KV; j++) {
                const ulonglong2 p1 = *(const ulonglong2*)&sW1[(k0 + j) * FOUT + c4];
                const ulonglong2 p2 = *(const ulonglong2*)&sW2[(k0 + j) * FOUT + c4];
                w1a[j] = p1.x; w1b[j] = p1.y;
                w2a[j] = p2.x; w2b[j] = p2.y;
            }
#pragma unroll
            for (int r = 0; r < R; r++) {
                if (row0 + r >= n) break;
                const float2 q = *(const float2*)&X[(size_t)(row0 + r) * FIN + k0];
                float xv[KV];
                xv[0] = q.x; xv[1] = q.y;
#pragma unroll
                for (int j = 0; j < KV; j++) {
                    const unsigned long long xx = pk2(xv[j], xv[j]);
                    fma2(acc1[r][0], xx, w1a[j]);
                    fma2(acc1[r][1], xx, w1b[j]);
                    fma2(acc2[r][0], xx, w2a[j]);
                    fma2(acc2[r][1], xx, w2b[j]);
                }
            }
        }
    }

    const float4 bb = *(const float4*)&sB[c4];
#pragma unroll
    for (int r = 0; r < R; r++) {
        int row = row0 + r;
        if (row < n) {
            float4 o1, o2;
            upk2(o1.x, o1.y, acc1[r][0]);
            upk2(o1.z, o1.w, acc1[r][1]);
            upk2(o2.x, o2.y, acc2[r][0]);
            upk2(o2.z, o2.w, acc2[r][1]);
            o2.x += bb.x; o2.y += bb.y; o2.z += bb.z; o2.w += bb.w;
            // pack 4 fp32 -> 4 bf16 (8B store)
            __nv_bfloat162 h01 = __floats2bfloat162_rn(o1.x, o1.y);
            __nv_bfloat162 h23 = __floats2bfloat162_rn(o1.z, o1.w);
            uint2 hp;
            hp.x = *(const unsigned*)&h01;
            hp.y = *(const unsigned*)&h23;
            *(uint2*)&H[(size_t)row * FOUT + c4] = hp;
            *(float4*)&A[(size_t)row * FOUT + c4] = o2;
        }
    }
}

// ---------------------------------------------------------------------------
// CSR build kernels (run every replay; graph-capturable)
// ---------------------------------------------------------------------------
__global__ void zero_misc_kernel(int n)
{
    int i = blockIdx.x * blockDim.x + threadIdx.x;
    if (i < n)       g_deg[i] = 0;
    if (i < GG * 32) g_pool[i] = 0.f;
    if (i < GG)      g_cnt[i]  = 0.f;
}

__global__ void hist_kernel(const int* __restrict__ er, int E)
{
    int e = blockIdx.x * blockDim.x + threadIdx.x;
    if (e < E) atomicAdd(&g_deg[__ldg(&er[e])], 1);
}

// block-level exclusive scan of g_deg -> g_rp (block-local), block totals -> g_bsum
__global__ void __launch_bounds__(SCAN_B) scan1_kernel(int n)
{
    __shared__ int wsum[32];
    int i = blockIdx.x * SCAN_B + threadIdx.x;
    int v = (i < n) ? g_deg[i] : 0;
    int lane = threadIdx.x & 31, wid = threadIdx.x >> 5;

    int s = v;
#pragma unroll
    for (int o = 1; o < 32; o <<= 1) {
        int t = __shfl_up_sync(0xFFFFFFFFu, s, o);
        if (lane >= o) s += t;
    }
    if (lane == 31) wsum[wid] = s;
    __syncthreads();
    if (wid == 0) {
        int ws = wsum[lane];
#pragma unroll
        for (int o = 1; o < 32; o <<= 1) {
            int t = __shfl_up_sync(0xFFFFFFFFu, ws, o);
            if (lane >= o) ws += t;
        }
        wsum[lane] = ws;
    }
    __syncthreads();
    int excl = s - v + ((wid > 0) ? wsum[wid - 1] : 0);
    if (i < n) g_rp[i] = excl;
    if (threadIdx.x == 0) g_bsum[blockIdx.x] = wsum[31];
}

// scan3 with inline block-prefix (fused scan2): each block reduces
// g_bsum[0..blockIdx-1] with one warp, then applies the offset.
__global__ void __launch_bounds__(SCAN_B) scan3_kernel(int n, int E)
{
    __shared__ int pfx;
    if (threadIdx.x < 32) {
        int s = 0;
        for (int j = threadIdx.x; j < blockIdx.x; j += 32) s += g_bsum[j];
#pragma unroll
        for (int o = 16; o > 0; o >>= 1)
            s += __shfl_xor_sync(0xFFFFFFFFu, s, o);
        if (threadIdx.x == 0) pfx = s;
    }
    __syncthreads();
    int i = blockIdx.x * SCAN_B + threadIdx.x;
    if (i < n) {
        int v = g_rp[i] + pfx;
        g_rp[i]  = v;
        g_cur[i] = v;
    }
    if (blockIdx.x == 0 && threadIdx.x == 0) g_rp[n] = E;
}

__global__ void fill_kernel(const int* __restrict__ er,
                            const int* __restrict__ ec,
                            const float* __restrict__ ew, int E)
{
    int e = blockIdx.x * blockDim.x + threadIdx.x;
    if (e >= E) return;
    int r   = __ldg(&er[e]);
    int pos = atomicAdd(&g_cur[r], 1);
    g_ssrc[pos] = __ldg(&ec[e]);
    g_sw[pos]   = __ldg(&ew[e]);
}

// ---------------------------------------------------------------------------
// Gather aggregation: one warp per destination row.
//   out[r,:] = relu( sum_{e in row r} w_e * bf16->f32(H[src_e,:]) + A[r,:] )
// ---------------------------------------------------------------------------
template <int FOUT, bool POOL>
__global__ void __launch_bounds__(256) agg_rows(
    const __nv_bfloat16* __restrict__ H,
    float* __restrict__ A,                 // in: xW2+b, out: activated result
    const int* __restrict__ seg,
    int n)
{
    constexpr int TPR = FOUT / 4;          // 32 / 16 / 8
    constexpr int EPI = 32 / TPR;          // 1 / 2 / 4

    int warp = (blockIdx.x * blockDim.x + threadIdx.x) >> 5;
    if (warp >= n) return;
    int lane = threadIdx.x & 31;
    int cl   = lane % TPR;                 // column chunk (4 bf16)
    int es   = lane / TPR;                 // edge slot

    int begin = __ldg(&g_rp[warp]);
    int end   = __ldg(&g_rp[warp + 1]);

    float4 acc = make_float4(0.f, 0.f, 0.f, 0.f);
#pragma unroll 2
    for (int i = begin + es; i < end; i += EPI) {
        int   src = __ldg(&g_ssrc[i]);
        float w   = __ldg(&g_sw[i]);
        const uint2 hp = *(const uint2*)&H[(size_t)src * FOUT + cl * 4];
        float2 f01 = __bfloat1622float2(*(const __nv_bfloat162*)&hp.x);
        float2 f23 = __bfloat1622float2(*(const __nv_bfloat162*)&hp.y);
        acc.x = fmaf(w, f01.x, acc.x);
        acc.y = fmaf(w, f01.y, acc.y);
        acc.z = fmaf(w, f23.x, acc.z);
        acc.w = fmaf(w, f23.y, acc.w);
    }

    // reduce edge-slot partials (lanes with equal cl)
#pragma unroll
    for (int off = TPR; off < 32; off <<= 1) {
        acc.x += __shfl_xor_sync(0xFFFFFFFFu, acc.x, off);
        acc.y += __shfl_xor_sync(0xFFFFFFFFu, acc.y, off);
        acc.z += __shfl_xor_sync(0xFFFFFFFFu, acc.z, off);
        acc.w += __shfl_xor_sync(0xFFFFFFFFu, acc.w, off);
    }

    if (es == 0) {
        const float4 base = *(const float4*)&A[(size_t)warp * FOUT + cl * 4];
        float4 o;
        o.x = fmaxf(acc.x + base.x, 0.f);
        o.y = fmaxf(acc.y + base.y, 0.f);
        o.z = fmaxf(acc.z + base.z, 0.f);
        o.w = fmaxf(acc.w + base.w, 0.f);
        if (POOL) {
            int g = __ldg(&seg[warp]);
            float* dst = &g_pool[g * 32 + cl * 4];
            asm volatile("red.global.add.v4.f32 [%0], {%1,%2,%3,%4};"
                         :: "l"(dst), "f"(o.x), "f"(o.y), "f"(o.z), "f"(o.w)
                         : "memory");
            if (cl == 0) atomicAdd(&g_cnt[g], 1.0f);
        } else {
            *(float4*)&A[(size_t)warp * FOUT + cl * 4] = o;
        }
    }
}

__global__ void head_kernel(const float* __restrict__ wd,
                            const float* __restrict__ bd,
                            float* __restrict__ out)
{
    int g = threadIdx.x;   // 256 threads, one per graph
    float cnt = fmaxf(g_cnt[g], 1.0f);
    float inv = 1.0f / cnt;
    float z0 = __ldg(&bd[0]);
    float z1 = __ldg(&bd[1]);
#pragma unroll
    for (int k = 0; k < 32; k++) {
        float p = g_pool[g * 32 + k] * inv;
        z0 = fmaf(p, __ldg(&wd[k * 2 + 0]), z0);
        z1 = fmaf(p, __ldg(&wd[k * 2 + 1]), z1);
    }
    float m  = fmaxf(z0, z1);
    float e0 = __expf(z0 - m);
    float e1 = __expf(z1 - m);
    float s  = 1.0f / (e0 + e1);
    out[g * 2 + 0] = e0 * s;
    out[g * 2 + 1] = e1 * s;
}

// ---------------------------------------------------------------------------
// Launch: CSR chain forked onto a side stream, overlapping the layer-1 GEMM.
// ---------------------------------------------------------------------------
extern "C" void kernel_launch(void* const* d_in, const int* in_sizes, int n_in,
                              void* d_out, int out_size)
{
    const float* x    = (const float*)d_in[0];
    const float* ew   = (const float*)d_in[1];
    const int*   er   = (const int*)  d_in[2];
    const int*   ec   = (const int*)  d_in[3];
    const int*   seg  = (const int*)  d_in[4];
    const float* w1_1 = (const float*)d_in[5];
    const float* w2_1 = (const float*)d_in[6];
    const float* b_1  = (const float*)d_in[7];
    const float* w1_2 = (const float*)d_in[8];
    const float* w2_2 = (const float*)d_in[9];
    const float* b_2  = (const float*)d_in[10];
    const float* w1_3 = (const float*)d_in[11];
    const float* w2_3 = (const float*)d_in[12];
    const float* b_3  = (const float*)d_in[13];
    const float* wd   = (const float*)d_in[14];
    const float* bd   = (const float*)d_in[15];
    float* out = (float*)d_out;

    const int n = in_sizes[0] / 30;   // 50000
    const int E = in_sizes[1];        // 800000

    __nv_bfloat16* H;
    float *A1, *A2, *A3;
    cudaGetSymbolAddress((void**)&H,  g_h);
    cudaGetSymbolAddress((void**)&A1, g_a1);
    cudaGetSymbolAddress((void**)&A2, g_a2);
    cudaGetSymbolAddress((void**)&A3, g_a3);

    // Side stream + events (created once; identical behavior every call).
    static cudaStream_t sB = nullptr;
    static cudaEvent_t  evFork = nullptr, evCSR = nullptr;
    if (sB == nullptr) {
        cudaStreamCreateWithFlags(&sB, cudaStreamNonBlocking);
        cudaEventCreateWithFlags(&evFork, cudaEventDisableTiming);
        cudaEventCreateWithFlags(&evCSR,  cudaEventDisableTiming);
    }

    // dynamic smem sizes: (2*FIN*FOUT + FOUT) * 4 bytes
    const int sm1 = (2 * 30  * 128 + 128) * 4;   // 31232
    const int sm2 = (2 * 128 * 64  + 64)  * 4;   // 65792 (>48KB: opt in)
    const int sm3 = (2 * 64  * 32  + 32)  * 4;   // 16512

    cudaFuncSetAttribute(gemm_dual<128, 64>,
                         cudaFuncAttributeMaxDynamicSharedMemorySize, sm2);

    const int agg_blocks = (n * 32 + 255) / 256;

    // ---- Fork: CSR build on side stream ----
    cudaEventRecord(evFork, 0);
    cudaStreamWaitEvent(sB, evFork, 0);
    zero_misc_kernel<<<(n + 255) / 256, 256, 0, sB>>>(n);
    hist_kernel<<<(E + 255) / 256, 256, 0, sB>>>(er, E);
    scan1_kernel<<<SCAN_NB, SCAN_B, 0, sB>>>(n);
    scan3_kernel<<<SCAN_NB, SCAN_B, 0, sB>>>(n, E);
    fill_kernel<<<(E + 255) / 256, 256, 0, sB>>>(er, ec, ew, E);
    cudaEventRecord(evCSR, sB);

    // ---- Main stream: layer-1 GEMM overlaps the CSR build ----
    {
        int rows_per_block = (256 / (128 / 4)) * 4;  // 32
        int blocks = (n + rows_per_block - 1) / rows_per_block;
        gemm_dual<30, 128><<<blocks, 256, sm1>>>(x, w1_1, w2_1, b_1, H, A1, n);
    }

    // ---- Join; layer-1 aggregation ----
    cudaStreamWaitEvent(0, evCSR, 0);
    agg_rows<128, false><<<agg_blocks, 256>>>(H, A1, seg, n);

    // ---- Layer 2: 128 -> 64 ----
    {
        int rows_per_block = (256 / (64 / 4)) * 4;   // 64
        int blocks = (n + rows_per_block - 1) / rows_per_block;
        gemm_dual<128, 64><<<blocks, 256, sm2>>>(A1, w1_2, w2_2, b_2, H, A2, n);
        agg_rows<64, false><<<agg_blocks, 256>>>(H, A2, seg, n);
    }
    // ---- Layer 3: 64 -> 32 (aggregation fuses relu + global pool) ----
    {
        int rows_per_block = (256 / (32 / 4)) * 4;   // 128
        int blocks = (n + rows_per_block - 1) / rows_per_block;
        gemm_dual<64, 32><<<blocks, 256, sm3>>>(A2, w1_3, w2_3, b_3, H, A3, n);
        agg_rows<32, true><<<agg_blocks, 256>>>(H, A3, seg, n);
    }

    // ---- Head ----
    head_kernel<<<1, GG>>>(wd, bd, out);
}